// round 2
// baseline (speedup 1.0000x reference)
#include <cuda_runtime.h>
#include <math.h>

// FeedForwardQuantum: out = cos(relu(x@W1 + b1) + theta) @ W2 + b2
// Split into two kernels via __device__ scratch g_z (z duplicated as (z,z) pairs):
//   K1: z = cos(relu(x@W1+b1)+theta)   [read-bound + fma]
//   K2: out = z@W2 + b2                [store-bound + fma, zero smem]
// All inner products use Blackwell packed fma.rn.f32x2 (FFMA2).

#define DDIM 1024
#define QDIM 16
#define R1 128          // rows per CTA, K1
#define T1 256
#define R2 64           // rows per CTA, K2
#define T2 256
#define NCHUNK 32       // 1024 / 32
#define XS_STRIDE 36
#define PS_STRIDE 17
#define MAXROWS 32768

typedef unsigned long long u64;

__device__ float g_z[(size_t)MAXROWS * 32];   // (z,z)-pair rows, 4MB static scratch

__device__ __forceinline__ void ffma2(u64 &d, u64 a, u64 b) {
    asm("fma.rn.f32x2 %0, %1, %2, %0;" : "+l"(d) : "l"(a), "l"(b));
}
__device__ __forceinline__ float2 unpk(u64 v) {
    float2 f;
    asm("mov.b64 {%0,%1}, %2;" : "=f"(f.x), "=f"(f.y) : "l"(v));
    return f;
}
__device__ __forceinline__ u64 pk(float x, float y) {
    u64 v;
    asm("mov.b64 %0, {%1,%2};" : "=l"(v) : "f"(x), "f"(y));
    return v;
}

// ---------------- K1: GEMM1 + activation -> g_z ----------------
// 256 threads, 128 rows/CTA. Thread (r = tid&127, h = tid>>7) handles row r,
// d-half h (16 of each 32-d chunk). W1 pair-interleaved in smem for direct
// broadcast LDS.128 -> FFMA2. x staged in 32-d chunks w/ register prefetch.
__global__ void __launch_bounds__(T1, 2)
ffq_k1(const float* __restrict__ x, const float* __restrict__ W1,
       const float* __restrict__ b1, const float* __restrict__ theta,
       int nRows)
{
    extern __shared__ float sm[];
    float* w1p = sm;                       // 16384 floats (pair-interleaved W1)
    float* xs  = w1p + DDIM * QDIM;        // 128*36 = 4608 floats
    float* ps  = xs + R1 * XS_STRIDE;      // 128*17 = 2176 floats (partials)
    float* b1s = ps + R1 * PS_STRIDE;      // 16
    float* ths = b1s + QDIM;               // 16

    const int tid  = threadIdx.x;
    const int row0 = blockIdx.x * R1;

    // stage W1 pair-interleaved: w1p[b*32 + 2q + p] = W1[(2b+p)*16 + q]
    for (int o = tid; o < DDIM * QDIM; o += T1) {
        int b = o >> 5, rr = o & 31, q = rr >> 1, p = rr & 1;
        w1p[o] = W1[(2 * b + p) * QDIM + q];
    }
    if (tid < QDIM) { b1s[tid] = b1[tid]; ths[tid] = theta[tid]; }

    const int r = tid & (R1 - 1);
    const int h = tid >> 7;

    u64 acc[QDIM];
#pragma unroll
    for (int q = 0; q < QDIM; q++) acc[q] = 0ULL;

    // staging: thread owns 4 float4s per chunk: row rb+32k, col quad c4
    const int c4 = (tid & 7) * 4;
    const int rb = tid >> 3;               // 0..31

    float4 pf[4];
#pragma unroll
    for (int k = 0; k < 4; k++) {
        int gr = row0 + rb + 32 * k;
        if (gr >= nRows) gr = nRows - 1;
        pf[k] = *reinterpret_cast<const float4*>(x + (size_t)gr * DDIM + c4);
    }

    for (int ch = 0; ch < NCHUNK; ch++) {
#pragma unroll
        for (int k = 0; k < 4; k++)
            *reinterpret_cast<float4*>(xs + (rb + 32 * k) * XS_STRIDE + c4) = pf[k];
        __syncthreads();

        if (ch + 1 < NCHUNK) {
            int dbn = (ch + 1) * 32;
#pragma unroll
            for (int k = 0; k < 4; k++) {
                int gr = row0 + rb + 32 * k;
                if (gr >= nRows) gr = nRows - 1;
                pf[k] = *reinterpret_cast<const float4*>(x + (size_t)gr * DDIM + dbn + c4);
            }
        }

        const float* xrow = xs + r * XS_STRIDE + 16 * h;
        const float* wch  = w1p + (ch * 32 + 16 * h) * QDIM;
#pragma unroll
        for (int db = 0; db < 16; db += 4) {
            ulonglong2 xv = *reinterpret_cast<const ulonglong2*>(xrow + db);
            const float* wb = wch + db * QDIM;
#pragma unroll
            for (int m = 0; m < 8; m++) {
                ulonglong2 w = *reinterpret_cast<const ulonglong2*>(wb + 4 * m);
                ffma2(acc[2 * m],     xv.x, w.x);
                ffma2(acc[2 * m + 1], xv.x, w.y);
            }
#pragma unroll
            for (int m = 0; m < 8; m++) {
                ulonglong2 w = *reinterpret_cast<const ulonglong2*>(wb + 32 + 4 * m);
                ffma2(acc[2 * m],     xv.y, w.x);
                ffma2(acc[2 * m + 1], xv.y, w.y);
            }
        }
        __syncthreads();
    }

    // combine halves, activation, write z pairs
    float hs[QDIM];
#pragma unroll
    for (int q = 0; q < QDIM; q++) {
        float2 a = unpk(acc[q]);
        hs[q] = a.x + a.y;
    }
    if (h == 1) {
#pragma unroll
        for (int q = 0; q < QDIM; q++) ps[r * PS_STRIDE + q] = hs[q];
    }
    __syncthreads();
    if (h == 0) {
#pragma unroll
        for (int q = 0; q < QDIM; q++) {
            float v = hs[q] + ps[r * PS_STRIDE + q] + b1s[q];
            v = fmaxf(v, 0.0f) + ths[q];
            float z = cosf(v);
            xs[r * XS_STRIDE + 2 * q]     = z;   // reuse xs as z staging
            xs[r * XS_STRIDE + 2 * q + 1] = z;
        }
    }
    __syncthreads();

    // coalesced copy of z pairs to global scratch
#pragma unroll
    for (int k = 0; k < 4; k++) {
        int idx = tid + T1 * k;
        int row = idx >> 3;
        int cc  = (idx & 7) * 4;
        int gr  = row0 + row;
        if (gr < nRows) {
            float4 v = *reinterpret_cast<const float4*>(xs + row * XS_STRIDE + cc);
            *reinterpret_cast<float4*>(g_z + (size_t)gr * 32 + cc) = v;
        }
    }
}

// ---------------- K2: out = z@W2 + b2 ----------------
// 256 threads, 64 rows/CTA. Thread owns 4 output cols; W2 slice in registers;
// z pairs via broadcast LDG (L1-hit); coalesced STG.128. No smem.
__global__ void __launch_bounds__(T2)
ffq_k2(const float* __restrict__ W2, const float* __restrict__ b2,
       float* __restrict__ out, int nRows)
{
    const int tid  = threadIdx.x;
    const int row0 = blockIdx.x * R2;
    const int dcol = 4 * tid;

    ulonglong2 w2r[QDIM];
#pragma unroll
    for (int q = 0; q < QDIM; q++)
        w2r[q] = *reinterpret_cast<const ulonglong2*>(W2 + q * DDIM + dcol);

    float4 b2v = *reinterpret_cast<const float4*>(b2 + dcol);
    const u64 b2p0 = pk(b2v.x, b2v.y);
    const u64 b2p1 = pk(b2v.z, b2v.w);

    for (int rr = 0; rr < R2; rr++) {
        int gr = row0 + rr;
        if (gr >= nRows) break;
        const ulonglong2* zr = reinterpret_cast<const ulonglong2*>(g_z + (size_t)gr * 32);
        u64 a0 = b2p0, a1 = b2p1;
#pragma unroll
        for (int m = 0; m < 8; m++) {
            ulonglong2 zd = zr[m];                 // (z_{2m},z_{2m}),(z_{2m+1},z_{2m+1})
            ffma2(a0, zd.x, w2r[2 * m].x);
            ffma2(a1, zd.x, w2r[2 * m].y);
            ffma2(a0, zd.y, w2r[2 * m + 1].x);
            ffma2(a1, zd.y, w2r[2 * m + 1].y);
        }
        float2 lo = unpk(a0), hi = unpk(a1);
        float4 o = make_float4(lo.x, lo.y, hi.x, hi.y);
        *reinterpret_cast<float4*>(out + (size_t)gr * DDIM + dcol) = o;
    }
}

extern "C" void kernel_launch(void* const* d_in, const int* in_sizes, int n_in,
                              void* d_out, int out_size) {
    const float* x     = (const float*)d_in[0];
    const float* W1    = (const float*)d_in[1];
    const float* b1    = (const float*)d_in[2];
    const float* theta = (const float*)d_in[3];
    const float* W2    = (const float*)d_in[4];
    const float* b2    = (const float*)d_in[5];
    float* out = (float*)d_out;

    int nRows = in_sizes[0] / DDIM;                       // 32768

    size_t smem1 = (size_t)(DDIM * QDIM + R1 * XS_STRIDE + R1 * PS_STRIDE + 2 * QDIM)
                   * sizeof(float);                       // ~92.8 KB
    static int attr_set = 0;
    if (!attr_set) {
        cudaFuncSetAttribute(ffq_k1, cudaFuncAttributeMaxDynamicSharedMemorySize,
                             (int)smem1);
        attr_set = 1;
    }

    int grid1 = (nRows + R1 - 1) / R1;                    // 256
    int grid2 = (nRows + R2 - 1) / R2;                    // 512

    ffq_k1<<<grid1, T1, smem1>>>(x, W1, b1, theta, nRows);
    ffq_k2<<<grid2, T2>>>(W2, b2, out, nRows);
}

// round 3
// speedup vs baseline: 1.5866x; 1.5866x over previous
#include <cuda_runtime.h>
#include <math.h>

// FeedForwardQuantum (fused, single kernel):
//   out = cos(relu(x@W1 + b1) + theta) @ W2 + b2
// x:[32768,1024] W1:[1024,16] W2:[16,1024]
//
// v3: R1 fused structure, smem cut to 92.8KB for 2 CTAs/SM (16 warps):
//  - 128 rows/CTA, 256 threads: GEMM1 uses 2 threads/row (d-halves).
//  - W1 pair-interleaved in smem -> broadcast LDS.128 feeds fma.rn.f32x2.
//  - x staged gmem->smem in 32-d chunks with register prefetch.
//  - z pairs written back into the xs region (no separate zs buffer).
//  - GEMM2: W2 in registers (thread owns 4 out cols), z broadcast LDS,
//    coalesced STG.128.

#define DDIM 1024
#define QDIM 16
#define ROWS 128
#define NTHREADS 256
#define NCHUNK 32
#define XS_STRIDE 36
#define PS_STRIDE 17

typedef unsigned long long u64;

__device__ __forceinline__ void ffma2(u64 &d, u64 a, u64 b) {
    asm("fma.rn.f32x2 %0, %1, %2, %0;" : "+l"(d) : "l"(a), "l"(b));
}
__device__ __forceinline__ float2 unpk(u64 v) {
    float2 f;
    asm("mov.b64 {%0,%1}, %2;" : "=f"(f.x), "=f"(f.y) : "l"(v));
    return f;
}
__device__ __forceinline__ u64 pk(float x, float y) {
    u64 v;
    asm("mov.b64 %0, {%1,%2};" : "=l"(v) : "f"(x), "f"(y));
    return v;
}

__global__ void __launch_bounds__(NTHREADS, 2)
ffq_fused(const float* __restrict__ x, const float* __restrict__ W1,
          const float* __restrict__ b1, const float* __restrict__ theta,
          const float* __restrict__ W2, const float* __restrict__ b2,
          float* __restrict__ out, int nRows)
{
    extern __shared__ float sm[];
    float* w1p = sm;                        // 16384 floats (pair-interleaved W1)
    float* xs  = w1p + DDIM * QDIM;         // 128*36 = 4608 floats (x chunks, then z)
    float* ps  = xs + ROWS * XS_STRIDE;     // 128*17 = 2176 floats (h-partials)
    float* b1s = ps + ROWS * PS_STRIDE;     // 16
    float* ths = b1s + QDIM;                // 16

    const int tid  = threadIdx.x;
    const int row0 = blockIdx.x * ROWS;

    // ---- stage W1 pair-interleaved: w1p[b*32 + 2q + p] = W1[(2b+p)*16 + q] ----
    for (int o = tid; o < DDIM * QDIM; o += NTHREADS) {
        int b = o >> 5, rr = o & 31, q = rr >> 1, p = rr & 1;
        w1p[o] = W1[(2 * b + p) * QDIM + q];
    }
    if (tid < QDIM) { b1s[tid] = b1[tid]; ths[tid] = theta[tid]; }

    const int r = tid & (ROWS - 1);         // row within CTA
    const int h = tid >> 7;                 // d-half (0/1)

    u64 acc[QDIM];
#pragma unroll
    for (int q = 0; q < QDIM; q++) acc[q] = 0ULL;

    // staging: thread owns 4 float4s per chunk: row rb+32k, col quad c4
    const int c4 = (tid & 7) * 4;
    const int rb = tid >> 3;                // 0..31

    float4 pf[4];
#pragma unroll
    for (int k = 0; k < 4; k++) {
        int gr = row0 + rb + 32 * k;
        if (gr >= nRows) gr = nRows - 1;
        pf[k] = *reinterpret_cast<const float4*>(x + (size_t)gr * DDIM + c4);
    }

    for (int ch = 0; ch < NCHUNK; ch++) {
#pragma unroll
        for (int k = 0; k < 4; k++)
            *reinterpret_cast<float4*>(xs + (rb + 32 * k) * XS_STRIDE + c4) = pf[k];
        __syncthreads();

        if (ch + 1 < NCHUNK) {
            int dbn = (ch + 1) * 32;
#pragma unroll
            for (int k = 0; k < 4; k++) {
                int gr = row0 + rb + 32 * k;
                if (gr >= nRows) gr = nRows - 1;
                pf[k] = *reinterpret_cast<const float4*>(x + (size_t)gr * DDIM + dbn + c4);
            }
        }

        const float* xrow = xs + r * XS_STRIDE + 16 * h;
        const float* wch  = w1p + (ch * 32 + 16 * h) * QDIM;
#pragma unroll
        for (int db = 0; db < 16; db += 4) {
            ulonglong2 xv = *reinterpret_cast<const ulonglong2*>(xrow + db);
            const float* wb = wch + db * QDIM;
#pragma unroll
            for (int m = 0; m < 8; m++) {
                ulonglong2 w = *reinterpret_cast<const ulonglong2*>(wb + 4 * m);
                ffma2(acc[2 * m],     xv.x, w.x);
                ffma2(acc[2 * m + 1], xv.x, w.y);
            }
#pragma unroll
            for (int m = 0; m < 8; m++) {
                ulonglong2 w = *reinterpret_cast<const ulonglong2*>(wb + 32 + 4 * m);
                ffma2(acc[2 * m],     xv.y, w.x);
                ffma2(acc[2 * m + 1], xv.y, w.y);
            }
        }
        __syncthreads();
    }

    // ---- combine d-halves, activation, write duplicated z pairs into xs ----
    float hs[QDIM];
#pragma unroll
    for (int q = 0; q < QDIM; q++) {
        float2 a = unpk(acc[q]);
        hs[q] = a.x + a.y;
    }
    if (h == 1) {
#pragma unroll
        for (int q = 0; q < QDIM; q++) ps[r * PS_STRIDE + q] = hs[q];
    }
    __syncthreads();
    if (h == 0) {
#pragma unroll
        for (int q = 0; q < QDIM; q++) {
            float v = hs[q] + ps[r * PS_STRIDE + q] + b1s[q];
            v = fmaxf(v, 0.0f) + ths[q];
            float z = cosf(v);
            xs[r * XS_STRIDE + 2 * q]     = z;
            xs[r * XS_STRIDE + 2 * q + 1] = z;
        }
    }
    __syncthreads();

    // ---- GEMM2: W2 in registers, z broadcast LDS, coalesced STG.128 ----
    const int dcol = 4 * tid;
    ulonglong2 w2r[QDIM];
#pragma unroll
    for (int q = 0; q < QDIM; q++)
        w2r[q] = *reinterpret_cast<const ulonglong2*>(W2 + q * DDIM + dcol);

    float4 b2v = *reinterpret_cast<const float4*>(b2 + dcol);
    const u64 b2p0 = pk(b2v.x, b2v.y);
    const u64 b2p1 = pk(b2v.z, b2v.w);

    for (int rr2 = 0; rr2 < ROWS; rr2++) {
        u64 a0 = b2p0, a1 = b2p1;
        const float* zr = xs + rr2 * XS_STRIDE;
#pragma unroll
        for (int m = 0; m < 8; m++) {
            ulonglong2 zd = *reinterpret_cast<const ulonglong2*>(zr + 4 * m);
            ffma2(a0, zd.x, w2r[2 * m].x);
            ffma2(a1, zd.x, w2r[2 * m].y);
            ffma2(a0, zd.y, w2r[2 * m + 1].x);
            ffma2(a1, zd.y, w2r[2 * m + 1].y);
        }
        int gr = row0 + rr2;
        if (gr < nRows) {
            float2 lo = unpk(a0), hi = unpk(a1);
            float4 o = make_float4(lo.x, lo.y, hi.x, hi.y);
            *reinterpret_cast<float4*>(out + (size_t)gr * DDIM + dcol) = o;
        }
    }
}

extern "C" void kernel_launch(void* const* d_in, const int* in_sizes, int n_in,
                              void* d_out, int out_size) {
    const float* x     = (const float*)d_in[0];
    const float* W1    = (const float*)d_in[1];
    const float* b1    = (const float*)d_in[2];
    const float* theta = (const float*)d_in[3];
    const float* W2    = (const float*)d_in[4];
    const float* b2    = (const float*)d_in[5];
    float* out = (float*)d_out;

    int nRows = in_sizes[0] / DDIM;                        // 32768
    int grid  = (nRows + ROWS - 1) / ROWS;                 // 256

    size_t smem = (size_t)(DDIM * QDIM + ROWS * XS_STRIDE + ROWS * PS_STRIDE + 2 * QDIM)
                  * sizeof(float);                         // ~92.8 KB
    static int attr_set = 0;
    if (!attr_set) {
        cudaFuncSetAttribute(ffq_fused, cudaFuncAttributeMaxDynamicSharedMemorySize,
                             (int)smem);
        attr_set = 1;
    }

    ffq_fused<<<grid, NTHREADS, smem>>>(x, W1, b1, theta, W2, b2, out, nRows);
}

// round 4
// speedup vs baseline: 1.6855x; 1.0624x over previous
#include <cuda_runtime.h>
#include <math.h>

// FeedForwardQuantum fused v4:
//   out = cos(relu(x@W1 + b1) + theta) @ W2 + b2
// GEMM1 ownership: thread = (row-pair p/p+64, d-half h, q-half qh):
//   2 rows x 8 q x 16d-slice  ->  per 4d: 8 w-LDS + 2 x-LDS : 32 FFMA2
// Double-buffered x staging (1 sync per chunk). z-dup + partial buffers
// alias the staging buffers. GEMM2: W2 in regs, 2-row unroll, STG.128.

#define DDIM 1024
#define QDIM 16
#define ROWS 128
#define NTH 256
#define NCHUNK 32
#define XSTR 36
#define PSTR 17

typedef unsigned long long u64;

__device__ __forceinline__ void ffma2(u64 &d, u64 a, u64 b) {
    asm("fma.rn.f32x2 %0, %1, %2, %0;" : "+l"(d) : "l"(a), "l"(b));
}
__device__ __forceinline__ float2 unpk(u64 v) {
    float2 f;
    asm("mov.b64 {%0,%1}, %2;" : "=f"(f.x), "=f"(f.y) : "l"(v));
    return f;
}
__device__ __forceinline__ u64 pk(float x, float y) {
    u64 v;
    asm("mov.b64 %0, {%1,%2};" : "=l"(v) : "f"(x), "f"(y));
    return v;
}

__global__ void __launch_bounds__(NTH, 2)
ffq_v4(const float* __restrict__ x, const float* __restrict__ W1,
       const float* __restrict__ b1, const float* __restrict__ theta,
       const float* __restrict__ W2, const float* __restrict__ b2,
       float* __restrict__ out, int nRows)
{
    extern __shared__ float sm[];
    float* w1p  = sm;                      // 16384 floats, pair-interleaved W1
    float* buf0 = w1p + DDIM * QDIM;       // 128*36 = 4608
    float* buf1 = buf0 + ROWS * XSTR;      // 4608
    float* b1s  = buf1 + ROWS * XSTR;      // 16
    float* ths  = b1s + QDIM;              // 16

    const int tid  = threadIdx.x;
    const int row0 = blockIdx.x * ROWS;

    // ---- stage W1 pair-interleaved: w1p[b*32 + 2q + p] = W1[(2b+p)*16+q] ----
    for (int o = tid; o < DDIM * QDIM; o += NTH) {
        int b = o >> 5, rr = o & 31, q = rr >> 1, pp = rr & 1;
        w1p[o] = W1[(2 * b + pp) * QDIM + q];
    }
    if (tid < QDIM) { b1s[tid] = b1[tid]; ths[tid] = theta[tid]; }

    const int p  = tid & 63;               // row-pair id: rows p, p+64
    const int qh = (tid >> 6) & 1;         // q-half
    const int h  = tid >> 7;               // d-half

    u64 acc[16];                           // [row(2)][q(8)]
#pragma unroll
    for (int i = 0; i < 16; i++) acc[i] = 0ULL;

    // staging: thread owns 4 float4s/chunk: row rb+32k, col-quad c4
    const int c4 = (tid & 7) * 4;
    const int rb = tid >> 3;
    const float* gp[4];
#pragma unroll
    for (int k = 0; k < 4; k++) {
        int gr = row0 + rb + 32 * k;
        if (gr >= nRows) gr = nRows - 1;
        gp[k] = x + (size_t)gr * DDIM + c4;
    }

    float4 pf[4];
#pragma unroll
    for (int k = 0; k < 4; k++) pf[k] = *reinterpret_cast<const float4*>(gp[k]);
    // prologue: chunk 0 into buf0
#pragma unroll
    for (int k = 0; k < 4; k++)
        *reinterpret_cast<float4*>(buf0 + (rb + 32 * k) * XSTR + c4) = pf[k];
    __syncthreads();

    for (int ch = 0; ch < NCHUNK; ch++) {
        float* cb = (ch & 1) ? buf1 : buf0;
        float* nb = (ch & 1) ? buf0 : buf1;

        if (ch + 1 < NCHUNK) {
            int dbn = (ch + 1) * 32;
#pragma unroll
            for (int k = 0; k < 4; k++)
                pf[k] = *reinterpret_cast<const float4*>(gp[k] + dbn);
        }

        const float* xr0 = cb + p * XSTR + 16 * h;
        const float* xr1 = xr0 + 64 * XSTR;
        const float* wch = w1p + (ch * 16 + 8 * h) * 32 + 16 * qh;

#pragma unroll
        for (int db = 0; db < 16; db += 4) {
            ulonglong2 xa = *reinterpret_cast<const ulonglong2*>(xr0 + db);
            ulonglong2 xb = *reinterpret_cast<const ulonglong2*>(xr1 + db);
            const float* wq = wch + (db >> 1) * 32;   // d-pair block b0
            ulonglong2 wA0 = *reinterpret_cast<const ulonglong2*>(wq);
            ulonglong2 wA1 = *reinterpret_cast<const ulonglong2*>(wq + 4);
            ulonglong2 wA2 = *reinterpret_cast<const ulonglong2*>(wq + 8);
            ulonglong2 wA3 = *reinterpret_cast<const ulonglong2*>(wq + 12);
            // b0 (d pair db,db+1): x-pair = xa.x / xb.x
            ffma2(acc[0], xa.x, wA0.x);  ffma2(acc[1], xa.x, wA0.y);
            ffma2(acc[2], xa.x, wA1.x);  ffma2(acc[3], xa.x, wA1.y);
            ffma2(acc[4], xa.x, wA2.x);  ffma2(acc[5], xa.x, wA2.y);
            ffma2(acc[6], xa.x, wA3.x);  ffma2(acc[7], xa.x, wA3.y);
            ffma2(acc[8],  xb.x, wA0.x); ffma2(acc[9],  xb.x, wA0.y);
            ffma2(acc[10], xb.x, wA1.x); ffma2(acc[11], xb.x, wA1.y);
            ffma2(acc[12], xb.x, wA2.x); ffma2(acc[13], xb.x, wA2.y);
            ffma2(acc[14], xb.x, wA3.x); ffma2(acc[15], xb.x, wA3.y);
            const float* wr = wq + 32;                 // d-pair block b1
            ulonglong2 wB0 = *reinterpret_cast<const ulonglong2*>(wr);
            ulonglong2 wB1 = *reinterpret_cast<const ulonglong2*>(wr + 4);
            ulonglong2 wB2 = *reinterpret_cast<const ulonglong2*>(wr + 8);
            ulonglong2 wB3 = *reinterpret_cast<const ulonglong2*>(wr + 12);
            ffma2(acc[0], xa.y, wB0.x);  ffma2(acc[1], xa.y, wB0.y);
            ffma2(acc[2], xa.y, wB1.x);  ffma2(acc[3], xa.y, wB1.y);
            ffma2(acc[4], xa.y, wB2.x);  ffma2(acc[5], xa.y, wB2.y);
            ffma2(acc[6], xa.y, wB3.x);  ffma2(acc[7], xa.y, wB3.y);
            ffma2(acc[8],  xb.y, wB0.x); ffma2(acc[9],  xb.y, wB0.y);
            ffma2(acc[10], xb.y, wB1.x); ffma2(acc[11], xb.y, wB1.y);
            ffma2(acc[12], xb.y, wB2.x); ffma2(acc[13], xb.y, wB2.y);
            ffma2(acc[14], xb.y, wB3.x); ffma2(acc[15], xb.y, wB3.y);
        }

        if (ch + 1 < NCHUNK) {
#pragma unroll
            for (int k = 0; k < 4; k++)
                *reinterpret_cast<float4*>(nb + (rb + 32 * k) * XSTR + c4) = pf[k];
        }
        __syncthreads();
    }

    // ---- combine d-halves (ps aliases buf0), activation, z-dup into buf1 ----
    float* ps = buf0;
    float hv[16];
#pragma unroll
    for (int i = 0; i < 16; i++) {
        float2 a = unpk(acc[i]);
        hv[i] = a.x + a.y;
    }
    if (h == 1) {
#pragma unroll
        for (int j = 0; j < 8; j++) {
            ps[p * PSTR + 8 * qh + j]        = hv[j];
            ps[(p + 64) * PSTR + 8 * qh + j] = hv[8 + j];
        }
    }
    __syncthreads();
    float* zb = buf1;
    if (h == 0) {
#pragma unroll
        for (int j = 0; j < 8; j++) {
            int q = 8 * qh + j;
            float v0 = hv[j] + ps[p * PSTR + q] + b1s[q];
            v0 = fmaxf(v0, 0.0f) + ths[q];
            float z0 = __cosf(v0);
            zb[p * XSTR + 2 * q]     = z0;
            zb[p * XSTR + 2 * q + 1] = z0;
            float v1 = hv[8 + j] + ps[(p + 64) * PSTR + q] + b1s[q];
            v1 = fmaxf(v1, 0.0f) + ths[q];
            float z1 = __cosf(v1);
            zb[(p + 64) * XSTR + 2 * q]     = z1;
            zb[(p + 64) * XSTR + 2 * q + 1] = z1;
        }
    }
    __syncthreads();

    // ---- GEMM2: W2 in regs, z broadcast LDS, 2-row unroll, STG.128 ----
    const int dcol = 4 * tid;
    ulonglong2 w2r[QDIM];
#pragma unroll
    for (int q = 0; q < QDIM; q++)
        w2r[q] = *reinterpret_cast<const ulonglong2*>(W2 + q * DDIM + dcol);

    float4 b2v = *reinterpret_cast<const float4*>(b2 + dcol);
    const u64 b2p0 = pk(b2v.x, b2v.y);
    const u64 b2p1 = pk(b2v.z, b2v.w);

    for (int rr = 0; rr < ROWS; rr += 2) {
        u64 a0 = b2p0, a1 = b2p1, c0 = b2p0, c1 = b2p1;
        const float* z0 = zb + rr * XSTR;
        const float* z1 = z0 + XSTR;
#pragma unroll
        for (int m = 0; m < 8; m++) {
            ulonglong2 zd0 = *reinterpret_cast<const ulonglong2*>(z0 + 4 * m);
            ulonglong2 zd1 = *reinterpret_cast<const ulonglong2*>(z1 + 4 * m);
            ffma2(a0, zd0.x, w2r[2 * m].x);
            ffma2(a1, zd0.x, w2r[2 * m].y);
            ffma2(a0, zd0.y, w2r[2 * m + 1].x);
            ffma2(a1, zd0.y, w2r[2 * m + 1].y);
            ffma2(c0, zd1.x, w2r[2 * m].x);
            ffma2(c1, zd1.x, w2r[2 * m].y);
            ffma2(c0, zd1.y, w2r[2 * m + 1].x);
            ffma2(c1, zd1.y, w2r[2 * m + 1].y);
        }
        int gr = row0 + rr;
        if (gr < nRows) {
            float2 lo = unpk(a0), hi = unpk(a1);
            *reinterpret_cast<float4*>(out + (size_t)gr * DDIM + dcol) =
                make_float4(lo.x, lo.y, hi.x, hi.y);
        }
        if (gr + 1 < nRows) {
            float2 lo = unpk(c0), hi = unpk(c1);
            *reinterpret_cast<float4*>(out + (size_t)(gr + 1) * DDIM + dcol) =
                make_float4(lo.x, lo.y, hi.x, hi.y);
        }
    }
}

extern "C" void kernel_launch(void* const* d_in, const int* in_sizes, int n_in,
                              void* d_out, int out_size) {
    const float* x     = (const float*)d_in[0];
    const float* W1    = (const float*)d_in[1];
    const float* b1    = (const float*)d_in[2];
    const float* theta = (const float*)d_in[3];
    const float* W2    = (const float*)d_in[4];
    const float* b2    = (const float*)d_in[5];
    float* out = (float*)d_out;

    int nRows = in_sizes[0] / DDIM;                    // 32768
    int grid  = (nRows + ROWS - 1) / ROWS;             // 256

    size_t smem = (size_t)(DDIM * QDIM + 2 * ROWS * XSTR + 2 * QDIM) * sizeof(float);
    static int attr_set = 0;
    if (!attr_set) {
        cudaFuncSetAttribute(ffq_v4, cudaFuncAttributeMaxDynamicSharedMemorySize,
                             (int)smem);
        attr_set = 1;
    }

    ffq_v4<<<grid, NTH, smem>>>(x, W1, b1, theta, W2, b2, out, nRows);
}